// round 1
// baseline (speedup 1.0000x reference)
#include <cuda_runtime.h>

// ---------------- problem constants ----------------
#define N_NODES   32000
#define NUM_GRAPHS 32
#define NPG       1000
#define N_EDGES   256000
#define IN_DIM    1024
#define HID       256
#define NC        8

// ---------------- scratch (device globals; no allocation allowed) ----------------
__device__ float d_Yl1 [N_NODES * HID];   // x @ Wl1
__device__ float d_Yr1 [N_NODES * HID];   // x @ Wr1
__device__ float d_Ya  [N_NODES * 16];    // cols 0-7: x@Wla, 8-15: x@Wra
__device__ float d_agg1[N_NODES * HID];   // edge-summed Yl1 (by dst)
__device__ float d_agga[N_NODES * NC];    // edge-summed Ya[:,0:8]
__device__ float d_cnt [N_NODES];         // in-degree
__device__ float d_Z   [N_NODES * HID];   // relu SAGE1 output
__device__ float d_Ss  [N_NODES * NC];    // softmax assignment
__device__ float d_Xp  [NUM_GRAPHS * NC * HID];
__device__ float d_Ap  [NUM_GRAPHS * NC * NC];

// ---------------- zero accumulators ----------------
__global__ __launch_bounds__(256) void zero_kernel() {
    int t = blockIdx.x * blockDim.x + threadIdx.x;
    int stride = gridDim.x * blockDim.x;
    for (int i = t; i < N_NODES * HID; i += stride) d_agg1[i] = 0.f;
    for (int i = t; i < N_NODES * NC;  i += stride) d_agga[i] = 0.f;
    for (int i = t; i < N_NODES;       i += stride) d_cnt[i]  = 0.f;
    for (int i = t; i < NUM_GRAPHS * NC * HID; i += stride) d_Xp[i] = 0.f;
    for (int i = t; i < NUM_GRAPHS * NC * NC;  i += stride) d_Ap[i] = 0.f;
}

// ---------------- big SGEMM: C[32000,256] = A[32000,1024] @ B[1024,256] ----------------
// BM=128, BN=64, BK=16, 256 threads, 8x4 outputs/thread.
__global__ __launch_bounds__(256) void sgemm128(const float* __restrict__ A,
                                                const float* __restrict__ Bw,
                                                int which_out) {
    float* Cc = which_out ? d_Yr1 : d_Yl1;
    __shared__ float As[16][136];   // padded to kill store-phase bank conflicts
    __shared__ float Bs[16][64];
    int tid = threadIdx.x;
    int rb = blockIdx.x * 128, cb = blockIdx.y * 64;
    int tx = tid & 15, ty = tid >> 4;

    float acc[8][4];
#pragma unroll
    for (int i = 0; i < 8; i++)
#pragma unroll
        for (int j = 0; j < 4; j++) acc[i][j] = 0.f;

    for (int k0 = 0; k0 < IN_DIM; k0 += 16) {
#pragma unroll
        for (int t = 0; t < 2; t++) {
            int idx = tid + t * 256;            // 512 float4 loads total
            int r = idx >> 2, c = idx & 3;
            float4 v = *reinterpret_cast<const float4*>(
                &A[(size_t)(rb + r) * IN_DIM + k0 + c * 4]);
            As[c * 4 + 0][r] = v.x; As[c * 4 + 1][r] = v.y;
            As[c * 4 + 2][r] = v.z; As[c * 4 + 3][r] = v.w;
        }
        {
            int r = tid >> 4, c4 = (tid & 15) * 4;
            *reinterpret_cast<float4*>(&Bs[r][c4]) =
                *reinterpret_cast<const float4*>(&Bw[(size_t)(k0 + r) * HID + cb + c4]);
        }
        __syncthreads();
#pragma unroll
        for (int k = 0; k < 16; k++) {
            float4 a0 = *reinterpret_cast<float4*>(&As[k][ty * 8]);
            float4 a1 = *reinterpret_cast<float4*>(&As[k][ty * 8 + 4]);
            float4 b0 = *reinterpret_cast<float4*>(&Bs[k][tx * 4]);
            float av[8] = {a0.x, a0.y, a0.z, a0.w, a1.x, a1.y, a1.z, a1.w};
            float bv[4] = {b0.x, b0.y, b0.z, b0.w};
#pragma unroll
            for (int i = 0; i < 8; i++)
#pragma unroll
                for (int j = 0; j < 4; j++) acc[i][j] += av[i] * bv[j];
        }
        __syncthreads();
    }
#pragma unroll
    for (int i = 0; i < 8; i++) {
        float4 v = make_float4(acc[i][0], acc[i][1], acc[i][2], acc[i][3]);
        *reinterpret_cast<float4*>(&Cc[(size_t)(rb + ty * 8 + i) * HID + cb + tx * 4]) = v;
    }
}

// ---------------- small GEMM: Ya[32000,16] = x @ [Wla | Wra] ----------------
// BM=128, BN=16, BK=32, 256 threads, 8x1 outputs/thread.
__global__ __launch_bounds__(256) void sgemm_small(const float* __restrict__ A,
                                                   const float* __restrict__ Wla,
                                                   const float* __restrict__ Wra) {
    __shared__ float As[32][136];
    __shared__ float Bs[32][16];
    int tid = threadIdx.x;
    int rb = blockIdx.x * 128;
    int tx = tid & 15, ty = tid >> 4;

    float acc[8];
#pragma unroll
    for (int i = 0; i < 8; i++) acc[i] = 0.f;

    for (int k0 = 0; k0 < IN_DIM; k0 += 32) {
#pragma unroll
        for (int t = 0; t < 4; t++) {
            int idx = tid + t * 256;            // 1024 float4 loads
            int r = idx >> 3, c = idx & 7;
            float4 v = *reinterpret_cast<const float4*>(
                &A[(size_t)(rb + r) * IN_DIM + k0 + c * 4]);
            As[c * 4 + 0][r] = v.x; As[c * 4 + 1][r] = v.y;
            As[c * 4 + 2][r] = v.z; As[c * 4 + 3][r] = v.w;
        }
#pragma unroll
        for (int t = 0; t < 2; t++) {
            int idx = tid + t * 256;            // 512 scalars
            int r = idx >> 4, c = idx & 15;
            Bs[r][c] = (c < 8) ? Wla[(size_t)(k0 + r) * 8 + c]
                               : Wra[(size_t)(k0 + r) * 8 + (c - 8)];
        }
        __syncthreads();
#pragma unroll
        for (int k = 0; k < 32; k++) {
            float4 a0 = *reinterpret_cast<float4*>(&As[k][ty * 8]);
            float4 a1 = *reinterpret_cast<float4*>(&As[k][ty * 8 + 4]);
            float b = Bs[k][tx];
            acc[0] += a0.x * b; acc[1] += a0.y * b; acc[2] += a0.z * b; acc[3] += a0.w * b;
            acc[4] += a1.x * b; acc[5] += a1.y * b; acc[6] += a1.z * b; acc[7] += a1.w * b;
        }
        __syncthreads();
    }
#pragma unroll
    for (int i = 0; i < 8; i++)
        d_Ya[(size_t)(rb + ty * 8 + i) * 16 + tx] = acc[i];
}

// ---------------- edge aggregation: one warp per edge ----------------
__global__ __launch_bounds__(256) void edge_agg(const int* __restrict__ src,
                                                const int* __restrict__ dst) {
    int w = (blockIdx.x * blockDim.x + threadIdx.x) >> 5;
    if (w >= N_EDGES) return;
    int lane = threadIdx.x & 31;
    int s = src[w], d = dst[w];
    const float* ys = d_Yl1 + (size_t)s * HID;
    float* ad = d_agg1 + (size_t)d * HID;
#pragma unroll
    for (int j = 0; j < 8; j++)
        atomicAdd(&ad[lane + 32 * j], ys[lane + 32 * j]);
    if (lane < 8) atomicAdd(&d_agga[d * NC + lane], d_Ya[s * 16 + lane]);
    if (lane == 0) atomicAdd(&d_cnt[d], 1.0f);
}

// ---------------- per-node finalize: Z = relu(agg/cnt + bl1 + Yr1); Ss = softmax(S) ----------------
__global__ __launch_bounds__(256) void node_fin(const float* __restrict__ bl1,
                                                const float* __restrict__ bla) {
    int w = (blockIdx.x * blockDim.x + threadIdx.x) >> 5;
    if (w >= N_NODES) return;
    int lane = threadIdx.x & 31;
    float c = d_cnt[w];
    float inv = (c > 0.f) ? 1.f / c : 0.f;
    size_t base = (size_t)w * HID;
#pragma unroll
    for (int j = 0; j < 8; j++) {
        int f = lane + 32 * j;
        float z = d_agg1[base + f] * inv + bl1[f] + d_Yr1[base + f];
        d_Z[base + f] = fmaxf(z, 0.f);
    }
    float sv = -1e30f;
    if (lane < 8)
        sv = d_agga[w * NC + lane] * inv + bla[lane] + d_Ya[w * 16 + 8 + lane];
    float m = sv;
    m = fmaxf(m, __shfl_xor_sync(0xffffffffu, m, 4));
    m = fmaxf(m, __shfl_xor_sync(0xffffffffu, m, 2));
    m = fmaxf(m, __shfl_xor_sync(0xffffffffu, m, 1));
    float e = (lane < 8) ? expf(sv - m) : 0.f;
    float ssum = e;
    ssum += __shfl_xor_sync(0xffffffffu, ssum, 4);
    ssum += __shfl_xor_sync(0xffffffffu, ssum, 2);
    ssum += __shfl_xor_sync(0xffffffffu, ssum, 1);
    if (lane < 8) d_Ss[w * NC + lane] = e / ssum;
}

// ---------------- Xp[g] = sum_{i in g} Ss_i (outer) Z_i ; 4 chunks/graph, register accum ----------------
__global__ __launch_bounds__(256) void xp_kernel() {
    int g = blockIdx.x >> 2, chunk = blockIdx.x & 3, tid = threadIdx.x;
    float acc[8];
#pragma unroll
    for (int c = 0; c < 8; c++) acc[c] = 0.f;
    int n0 = g * NPG + chunk * 250;
    for (int n = n0; n < n0 + 250; n++) {
        const float4* sp = reinterpret_cast<const float4*>(&d_Ss[n * NC]);
        float4 v0 = sp[0], v1 = sp[1];               // broadcast L1 loads
        float z = d_Z[(size_t)n * HID + tid];        // coalesced
        acc[0] += v0.x * z; acc[1] += v0.y * z; acc[2] += v0.z * z; acc[3] += v0.w * z;
        acc[4] += v1.x * z; acc[5] += v1.y * z; acc[6] += v1.z * z; acc[7] += v1.w * z;
    }
#pragma unroll
    for (int c = 0; c < 8; c++)
        atomicAdd(&d_Xp[g * (NC * HID) + c * HID + tid], acc[c]);
}

// ---------------- Ap[g] += Ss[src] (outer) Ss[dst] per edge ----------------
// Warp-private SMEM copies, conflict-free lane->pair mapping, no SMEM atomics.
__global__ __launch_bounds__(128) void ap_kernel(const int* __restrict__ src,
                                                 const int* __restrict__ dst) {
    __shared__ float apl[4 * NUM_GRAPHS * 64];   // 4 warp-private [32][64] copies = 32KB
    int tid = threadIdx.x, wid = tid >> 5, lane = tid & 31;
    for (int i = tid; i < 4 * NUM_GRAPHS * 64; i += 128) apl[i] = 0.f;
    __syncthreads();
    float* my = apl + wid * (NUM_GRAPHS * 64);
    int gw = blockIdx.x * 4 + wid;                // 0..3999 ; each warp: 64 edges
#pragma unroll
    for (int b = 0; b < 2; b++) {
        int e = gw * 64 + b * 32 + lane;
        int s = src[e], d = dst[e];
        for (int j = 0; j < 32; j++) {
            int sj = __shfl_sync(0xffffffffu, s, j);
            int dj = __shfl_sync(0xffffffffu, d, j);
            int gj = sj / NPG;
            float v = 0.f;
            if (lane < 8)       v = d_Ss[sj * NC + lane];
            else if (lane < 16) v = d_Ss[dj * NC + (lane - 8)];
            int a1 = lane >> 3;                   // 0..3
            int bb = lane & 7;
            float s1 = __shfl_sync(0xffffffffu, v, a1);
            float s2 = __shfl_sync(0xffffffffu, v, a1 + 4);
            float sd = __shfl_sync(0xffffffffu, v, 8 + bb);
            float* p = my + gj * 64;
            p[lane]      += s1 * sd;              // pair (a1, bb)   == index lane
            p[lane + 32] += s2 * sd;              // pair (a1+4, bb) == index lane+32
        }
    }
    __syncthreads();
    for (int i = tid; i < NUM_GRAPHS * 64; i += 128) {
        float a = apl[i] + apl[NUM_GRAPHS * 64 + i] +
                  apl[2 * NUM_GRAPHS * 64 + i] + apl[3 * NUM_GRAPHS * 64 + i];
        atomicAdd(&d_Ap[i], a);
    }
}

// ---------------- pooled DiffPool conv + classifier: one block per graph ----------------
__global__ __launch_bounds__(256) void final_kernel(const float* __restrict__ Wl2,
                                                    const float* __restrict__ bl2,
                                                    const float* __restrict__ Wr2,
                                                    const float* __restrict__ Wc1,
                                                    const float* __restrict__ bc1,
                                                    const float* __restrict__ Wc2,
                                                    const float* __restrict__ bc2,
                                                    float* __restrict__ out) {
    int g = blockIdx.x, tid = threadIdx.x;
    __shared__ float maskS[64];
    __shared__ float degS[8];
    __shared__ float xps[8 * 256];
    __shared__ float a2s[8 * 256];
    __shared__ float zps[2048];
    __shared__ float red[256];

    if (tid < 64) maskS[tid] = (d_Ap[g * 64 + tid] != 0.0f) ? 1.0f : 0.0f;
    __syncthreads();
    if (tid < 8) {
        float dg = 0.f;
#pragma unroll
        for (int i = 0; i < 8; i++) dg += maskS[i * 8 + tid];
        degS[tid] = dg;
    }
#pragma unroll
    for (int c = 0; c < 8; c++)
        xps[c * 256 + tid] = d_Xp[g * 2048 + c * 256 + tid];
    __syncthreads();

    // agg2[j][h] = mean over source pooled nodes i with mask[i][j]
#pragma unroll
    for (int j = 0; j < 8; j++) {
        float s = 0.f;
#pragma unroll
        for (int i = 0; i < 8; i++) s += maskS[i * 8 + j] * xps[i * 256 + tid];
        float dg = degS[j];
        a2s[j * 256 + tid] = (dg > 0.f) ? s / fmaxf(dg, 1.f) : 0.f;
    }
    __syncthreads();

    // Zp[j][h] = relu(agg2[j]@Wl2 + bl2 + Xp[j]@Wr2)
    float acc[8];
    float bb = bl2[tid];
#pragma unroll
    for (int j = 0; j < 8; j++) acc[j] = bb;
    for (int k = 0; k < 256; k++) {
        float wl = Wl2[k * 256 + tid];
        float wr = Wr2[k * 256 + tid];
#pragma unroll
        for (int j = 0; j < 8; j++)
            acc[j] += a2s[j * 256 + k] * wl + xps[j * 256 + k] * wr;
    }
#pragma unroll
    for (int j = 0; j < 8; j++) zps[j * 256 + tid] = fmaxf(acc[j], 0.f);
    __syncthreads();

    // classifier: h = relu(flatten(Zp) @ Wc1 + bc1); out = h @ Wc2 + bc2
    float hacc = bc1[tid];
    for (int m = 0; m < 2048; m++) hacc += zps[m] * Wc1[m * 256 + tid];
    float hv = fmaxf(hacc, 0.f);
    red[tid] = hv * Wc2[tid];
    __syncthreads();
    for (int s = 128; s > 0; s >>= 1) {
        if (tid < s) red[tid] += red[tid + s];
        __syncthreads();
    }
    if (tid == 0) out[g] = red[0] + bc2[0];
}

// ---------------- launch ----------------
extern "C" void kernel_launch(void* const* d_in, const int* in_sizes, int n_in,
                              void* d_out, int out_size) {
    const float* x   = (const float*)d_in[0];
    const int*   ei  = (const int*)d_in[1];
    const int*   src = ei;
    const int*   dst = ei + N_EDGES;
    const float* Wl1 = (const float*)d_in[3];
    const float* bl1 = (const float*)d_in[4];
    const float* Wr1 = (const float*)d_in[5];
    const float* Wla = (const float*)d_in[6];
    const float* bla = (const float*)d_in[7];
    const float* Wra = (const float*)d_in[8];
    const float* Wl2 = (const float*)d_in[9];
    const float* bl2 = (const float*)d_in[10];
    const float* Wr2 = (const float*)d_in[11];
    const float* Wc1 = (const float*)d_in[12];
    const float* bc1 = (const float*)d_in[13];
    const float* Wc2 = (const float*)d_in[14];
    const float* bc2 = (const float*)d_in[15];
    float* out = (float*)d_out;

    zero_kernel<<<2048, 256>>>();
    sgemm128<<<dim3(250, 4), 256>>>(x, Wl1, 0);
    sgemm128<<<dim3(250, 4), 256>>>(x, Wr1, 1);
    sgemm_small<<<250, 256>>>(x, Wla, Wra);
    edge_agg<<<32000, 256>>>(src, dst);
    node_fin<<<4000, 256>>>(bl1, bla);
    xp_kernel<<<128, 256>>>();
    ap_kernel<<<1000, 128>>>(src, dst);
    final_kernel<<<32, 256>>>(Wl2, bl2, Wr2, Wc1, bc1, Wc2, bc2, out);
}

// round 5
// speedup vs baseline: 1.5741x; 1.5741x over previous
#include <cuda_runtime.h>
#include <cuda_bf16.h>
#include <cstdint>

// ---------------- problem constants ----------------
#define N_NODES   32000
#define NUM_GRAPHS 32
#define NPG       1000
#define N_EDGES   256000
#define IN_DIM    1024
#define HID       256
#define NC        8

// ---------------- scratch (device globals) ----------------
__device__ float d_Yl1 [N_NODES * HID];
__device__ float d_Yr1 [N_NODES * HID];
__device__ float d_Ya  [N_NODES * 16];
__device__ float d_Z   [N_NODES * HID];
__device__ float d_Ss  [N_NODES * NC];
__device__ float d_Xp  [NUM_GRAPHS * NC * HID];
__device__ float d_Ap  [NUM_GRAPHS * NC * NC];
__device__ __nv_bfloat16 d_Bhi[528 * 1024];
__device__ __nv_bfloat16 d_Blo[528 * 1024];
// CSR for dst-sorted edges
__device__ int d_deg [N_NODES];
__device__ int d_off [N_NODES];
__device__ int d_cur [N_NODES];
__device__ int d_srcs[N_EDGES];

// =============== helpers (sm_80-era PTX: valid under compute_100) ===============
static __device__ __forceinline__ uint32_t s2u(const void* p) {
    uint32_t a;
    asm("{ .reg .u64 t; cvta.to.shared.u64 t, %1; cvt.u32.u64 %0, t; }" : "=r"(a) : "l"(p));
    return a;
}
#define LDMX4(r0, r1, r2, r3, addr) \
    asm volatile("ldmatrix.sync.aligned.m8n8.x4.shared.b16 {%0,%1,%2,%3}, [%4];" \
        : "=r"(r0), "=r"(r1), "=r"(r2), "=r"(r3) : "r"(addr))
#define MMA16816(c, a, b) \
    asm volatile("mma.sync.aligned.m16n8k16.row.col.f32.bf16.bf16.f32 " \
        "{%0,%1,%2,%3}, {%4,%5,%6,%7}, {%8,%9}, {%0,%1,%2,%3};" \
        : "+f"((c)[0]), "+f"((c)[1]), "+f"((c)[2]), "+f"((c)[3]) \
        : "r"((a)[0]), "r"((a)[1]), "r"((a)[2]), "r"((a)[3]), "r"((b)[0]), "r"((b)[1]))
#define CP16(dst, src) \
    asm volatile("cp.async.cg.shared.global [%0], [%1], 16;" :: "r"(dst), "l"(src))
#define CPCOMMIT() asm volatile("cp.async.commit_group;" ::: "memory")
#define CPWAIT0()  asm volatile("cp.async.wait_group 0;" ::: "memory")

// ---------------- zero small accumulators ----------------
__global__ __launch_bounds__(256) void zero_kernel() {
    int t = blockIdx.x * blockDim.x + threadIdx.x;
    int stride = gridDim.x * blockDim.x;
    for (int i = t; i < N_NODES; i += stride) d_deg[i] = 0;
    for (int i = t; i < NUM_GRAPHS * NC * HID; i += stride) d_Xp[i] = 0.f;
    for (int i = t; i < NUM_GRAPHS * NC * NC;  i += stride) d_Ap[i] = 0.f;
}

// ---------------- weight prep: transpose + bf16 hi/lo split ----------------
__global__ __launch_bounds__(256) void prep_b(const float* __restrict__ Wl1,
                                              const float* __restrict__ Wr1,
                                              const float* __restrict__ Wla,
                                              const float* __restrict__ Wra) {
    int n = blockIdx.x;
    for (int k = threadIdx.x; k < IN_DIM; k += blockDim.x) {
        float w;
        if (n < 256)      w = Wl1[k * 256 + n];
        else if (n < 512) w = Wr1[k * 256 + (n - 256)];
        else if (n < 520) w = Wla[k * 8 + (n - 512)];
        else              w = Wra[k * 8 + (n - 520)];
        __nv_bfloat16 h = __float2bfloat16(w);
        d_Bhi[n * IN_DIM + k] = h;
        d_Blo[n * IN_DIM + k] = __float2bfloat16(w - __bfloat162float(h));
    }
}

// ---------------- CSR build ----------------
__global__ __launch_bounds__(256) void hist_kernel(const int* __restrict__ dst) {
    int t = blockIdx.x * blockDim.x + threadIdx.x;
    int stride = gridDim.x * blockDim.x;
    for (int e = t; e < N_EDGES; e += stride) atomicAdd(&d_deg[dst[e]], 1);
}

__global__ __launch_bounds__(1024) void scan_kernel() {
    __shared__ int part[1024];
    int t = threadIdx.x;
    int base = t * 32;
    int s = 0;
    if (base < N_NODES) {
        int lim = min(base + 32, N_NODES);
        for (int i = base; i < lim; i++) s += d_deg[i];
    }
    part[t] = s;
    __syncthreads();
    for (int off = 1; off < 1024; off <<= 1) {
        int v = (t >= off) ? part[t - off] : 0;
        __syncthreads();
        part[t] += v;
        __syncthreads();
    }
    int excl = (t == 0) ? 0 : part[t - 1];
    if (base < N_NODES) {
        int lim = min(base + 32, N_NODES);
        int run = excl;
        for (int i = base; i < lim; i++) {
            d_off[i] = run; d_cur[i] = run; run += d_deg[i];
        }
    }
}

__global__ __launch_bounds__(256) void scatter_kernel(const int* __restrict__ src,
                                                      const int* __restrict__ dst) {
    int t = blockIdx.x * blockDim.x + threadIdx.x;
    int stride = gridDim.x * blockDim.x;
    for (int e = t; e < N_EDGES; e += stride) {
        int pos = atomicAdd(&d_cur[dst[e]], 1);
        d_srcs[pos] = src[e];
    }
}

// ---------------- main tensor-core GEMM ----------------
// C[32000,256] = X[32000,1024] @ W^T, split-bf16 (3 products). grid (250, 2).
#define PADA 40
#define A_SZ (128 * PADA * 2)              // 10240 B per split
#define B_SZ (256 * PADA * 2)              // 20480 B per split
#define OFF_ALO A_SZ
#define OFF_BHI (2 * A_SZ)
#define OFF_BLO (2 * A_SZ + B_SZ)
#define STG (2 * A_SZ + 2 * B_SZ)          // 61440
#define GEMM_SMEM (2 * STG)                // 122880

// store nfl floats as hi/lo bf16; lo region begins at stage+lo_off
static __device__ __forceinline__ void split_sts(char* stage, const float* areg,
                                                 uint32_t off, int nfl, uint32_t lo_off) {
    uint32_t hi[8], lo[8];
#pragma unroll
    for (int j = 0; j < 8; j++) {
        if (j * 2 >= nfl) break;
        __nv_bfloat162 hp, lp;
        float f0 = areg[2 * j], f1 = areg[2 * j + 1];
        hp.x = __float2bfloat16(f0);
        hp.y = __float2bfloat16(f1);
        lp.x = __float2bfloat16(f0 - __bfloat162float(hp.x));
        lp.y = __float2bfloat16(f1 - __bfloat162float(hp.y));
        hi[j] = *reinterpret_cast<uint32_t*>(&hp);
        lo[j] = *reinterpret_cast<uint32_t*>(&lp);
    }
    *reinterpret_cast<uint4*>(stage + off)           = make_uint4(hi[0], hi[1], hi[2], hi[3]);
    *reinterpret_cast<uint4*>(stage + lo_off + off)  = make_uint4(lo[0], lo[1], lo[2], lo[3]);
    if (nfl == 16) {
        *reinterpret_cast<uint4*>(stage + off + 16)          = make_uint4(hi[4], hi[5], hi[6], hi[7]);
        *reinterpret_cast<uint4*>(stage + lo_off + off + 16) = make_uint4(lo[4], lo[5], lo[6], lo[7]);
    }
}

__global__ __launch_bounds__(256, 1) void mma_gemm(const float* __restrict__ X) {
    extern __shared__ char sm[];
    uint32_t sb = s2u(sm);
    int tid = threadIdx.x, lane = tid & 31, wid = tid >> 5;
    int rb = blockIdx.x * 128, yt = blockIdx.y;

    // loader roles
    int arow = tid >> 1, ahalf = (tid & 1) * 16;
    const float* aptr = X + (size_t)(rb + arow) * IN_DIM + ahalf;
    uint32_t a_sts = (uint32_t)(arow * PADA + ahalf) * 2;
    const char* bh_g = (const char*)(d_Bhi + ((size_t)yt * 256 + tid) * IN_DIM);
    const char* bl_g = (const char*)(d_Blo + ((size_t)yt * 256 + tid) * IN_DIM);
    uint32_t b_sts = (uint32_t)(tid * PADA) * 2;

    // compute addressing
    int wm = wid >> 2, wn = wid & 3;
    int tl = lane >> 3, tr = lane & 7;
    uint32_t a_off[4], b_off[4];
#pragma unroll
    for (int mf = 0; mf < 4; mf++) {
        int m_loc = wm * 64 + mf * 16 + (tl & 1) * 8 + tr;
        a_off[mf] = (uint32_t)(m_loc * PADA + (tl >> 1) * 8) * 2;
    }
#pragma unroll
    for (int ng = 0; ng < 4; ng++) {
        int n_loc = wn * 64 + ng * 16 + (tl >> 1) * 8 + tr;
        b_off[ng] = (uint32_t)(n_loc * PADA + (tl & 1) * 8) * 2;
    }

    float acc[4][8][4];
#pragma unroll
    for (int i = 0; i < 4; i++)
#pragma unroll
        for (int j = 0; j < 8; j++)
#pragma unroll
            for (int k = 0; k < 4; k++) acc[i][j][k] = 0.f;

    float areg[16];
    // ---- prologue: tile 0 ----
    {
        const float4* p = (const float4*)aptr;
#pragma unroll
        for (int i = 0; i < 4; i++) {
            float4 v = p[i];
            areg[4 * i] = v.x; areg[4 * i + 1] = v.y; areg[4 * i + 2] = v.z; areg[4 * i + 3] = v.w;
        }
#pragma unroll
        for (int i = 0; i < 4; i++) {
            CP16(sb + OFF_BHI + b_sts + i * 16, bh_g + i * 16);
            CP16(sb + OFF_BLO + b_sts + i * 16, bl_g + i * 16);
        }
        CPCOMMIT();
        split_sts(sm, areg, a_sts, 16, OFF_ALO);
        CPWAIT0();
        __syncthreads();
    }

    for (int t = 0; t < 32; t++) {
        uint32_t cur = (uint32_t)(t & 1) * STG;
        uint32_t nxt = (uint32_t)((t + 1) & 1) * STG;
        if (t < 31) {
            const float4* p = (const float4*)(aptr + (t + 1) * 32);
#pragma unroll
            for (int i = 0; i < 4; i++) {
                float4 v = p[i];
                areg[4 * i] = v.x; areg[4 * i + 1] = v.y; areg[4 * i + 2] = v.z; areg[4 * i + 3] = v.w;
            }
#pragma unroll
            for (int i = 0; i < 4; i++) {
                CP16(sb + nxt + OFF_BHI + b_sts + i * 16, bh_g + (size_t)(t + 1) * 64 + i * 16);
                CP16(sb + nxt + OFF_BLO + b_sts + i * 16, bl_g + (size_t)(t + 1) * 64 + i * 16);
            }
            CPCOMMIT();
        }
        uint32_t stb = sb + cur;
#pragma unroll
        for (int kk = 0; kk < 2; kk++) {
            uint32_t kb = kk * 32;
            uint32_t bh[4][4], blr[4][4], af[4][4];
#pragma unroll
            for (int ng = 0; ng < 4; ng++)
                LDMX4(bh[ng][0], bh[ng][1], bh[ng][2], bh[ng][3], stb + OFF_BHI + b_off[ng] + kb);
#pragma unroll
            for (int ng = 0; ng < 4; ng++)
                LDMX4(blr[ng][0], blr[ng][1], blr[ng][2], blr[ng][3], stb + OFF_BLO + b_off[ng] + kb);
#pragma unroll
            for (int mf = 0; mf < 4; mf++)
                LDMX4(af[mf][0], af[mf][1], af[mf][2], af[mf][3], stb + a_off[mf] + kb);
#pragma unroll
            for (int mf = 0; mf < 4; mf++)
#pragma unroll
                for (int ng = 0; ng < 4; ng++)
#pragma unroll
                    for (int h = 0; h < 2; h++)
                        MMA16816(acc[mf][ng * 2 + h], af[mf], &bh[ng][h * 2]);
#pragma unroll
            for (int mf = 0; mf < 4; mf++)
#pragma unroll
                for (int ng = 0; ng < 4; ng++)
#pragma unroll
                    for (int h = 0; h < 2; h++)
                        MMA16816(acc[mf][ng * 2 + h], af[mf], &blr[ng][h * 2]);
#pragma unroll
            for (int mf = 0; mf < 4; mf++)
                LDMX4(af[mf][0], af[mf][1], af[mf][2], af[mf][3], stb + OFF_ALO + a_off[mf] + kb);
#pragma unroll
            for (int mf = 0; mf < 4; mf++)
#pragma unroll
                for (int ng = 0; ng < 4; ng++)
#pragma unroll
                    for (int h = 0; h < 2; h++)
                        MMA16816(acc[mf][ng * 2 + h], af[mf], &bh[ng][h * 2]);
        }
        if (t < 31) split_sts(sm + nxt, areg, a_sts, 16, OFF_ALO);
        CPWAIT0();
        __syncthreads();
    }

    // ---- epilogue: direct global stores ----
    float* outp = yt ? d_Yr1 : d_Yl1;
    int qr = lane >> 2, qc = lane & 3;
#pragma unroll
    for (int mf = 0; mf < 4; mf++)
#pragma unroll
        for (int h = 0; h < 2; h++) {
            int m = rb + wm * 64 + mf * 16 + qr + 8 * h;
            float* orow = outp + (size_t)m * HID + wn * 64 + qc * 2;
#pragma unroll
            for (int nf = 0; nf < 8; nf++)
                *reinterpret_cast<float2*>(orow + nf * 8) =
                    make_float2(acc[mf][nf][2 * h], acc[mf][nf][2 * h + 1]);
        }
}

// ---------------- Ya GEMM: [32000,16] = X @ [Wla|Wra], mma split-bf16 ----------------
#define PAD2 24
#define A2_SZ (128 * PAD2 * 2)             // 6144
#define B2_SZ (16 * PAD2 * 2)              // 768
#define Y_ALO A2_SZ
#define Y_BHI (2 * A2_SZ)
#define Y_BLO (2 * A2_SZ + B2_SZ)
#define STG2 (2 * A2_SZ + 2 * B2_SZ)       // 13824

__global__ __launch_bounds__(256) void ya_gemm(const float* __restrict__ X) {
    __shared__ char sm2[2 * STG2];
    uint32_t sb = s2u(sm2);
    int tid = threadIdx.x, lane = tid & 31, wid = tid >> 5;
    int rb = blockIdx.x * 128;

    int arow = tid >> 1, ahalf = (tid & 1) * 8;
    const float* aptr = X + (size_t)(rb + arow) * IN_DIM + ahalf;
    uint32_t a_sts = (uint32_t)(arow * PAD2 + ahalf) * 2;

    int isb = (tid < 64);
    int bs = tid >> 5;           // 0 = hi, 1 = lo (valid when tid<64)
    int bi = tid & 31, brow = bi >> 1, bc = bi & 1;
    const char* bg = (const char*)((bs ? d_Blo : d_Bhi) + (size_t)(512 + brow) * IN_DIM);
    uint32_t b_sts = (bs ? Y_BLO : Y_BHI) + (uint32_t)(brow * PAD2 + bc * 8) * 2;

    int tl = lane >> 3, tr = lane & 7;
    uint32_t a_off = (uint32_t)((wid * 16 + (tl & 1) * 8 + tr) * PAD2 + (tl >> 1) * 8) * 2;
    uint32_t b_off = (uint32_t)(((tl >> 1) * 8 + tr) * PAD2 + (tl & 1) * 8) * 2;

    float acc[2][4];
#pragma unroll
    for (int i = 0; i < 2; i++)
#pragma unroll
        for (int k = 0; k < 4; k++) acc[i][k] = 0.f;

    float areg[8];
    {
        const float4* p = (const float4*)aptr;
#pragma unroll
        for (int i = 0; i < 2; i++) {
            float4 v = p[i];
            areg[4 * i] = v.x; areg[4 * i + 1] = v.y; areg[4 * i + 2] = v.z; areg[4 * i + 3] = v.w;
        }
        if (isb) CP16(sb + b_sts, bg + bc * 16);
        CPCOMMIT();
        split_sts(sm2, areg, a_sts, 8, Y_ALO);
        CPWAIT0();
        __syncthreads();
    }
    for (int t = 0; t < 64; t++) {
        uint32_t cur = (uint32_t)(t & 1) * STG2;
        uint32_t nxt = (uint32_t)((t + 1) & 1) * STG2;
        if (t < 63) {
            const float4* p = (const float4*)(aptr + (t + 1) * 16);
#pragma unroll
            for (int i = 0; i < 2; i++) {
                float4 v = p[i];
                areg[4 * i] = v.x; areg[4 * i + 1] = v.y; areg[4 * i + 2] = v.z; areg[4 * i + 3] = v.w;
            }
            if (isb) CP16(sb + nxt + b_sts, bg + (size_t)(t + 1) * 32 + bc * 16);
            CPCOMMIT();
        }
        uint32_t stb = sb + cur;
        {
            uint32_t bh[4], bl4[4], af[4];
            LDMX4(bh[0], bh[1], bh[2], bh[3], stb + Y_BHI + b_off);
            LDMX4(bl4[0], bl4[1], bl4[2], bl4[3], stb + Y_BLO + b_off);
            LDMX4(af[0], af[1], af[2], af[3], stb + a_off);
#pragma unroll
            for (int h = 0; h < 2; h++) {
                MMA16816(acc[h], af, &bh[h * 2]);
                MMA16816(acc[h], af, &bl4[h * 2]);
            }
            LDMX4(af[0], af[1], af[2], af[3], stb + Y_ALO + a_off);
#pragma unroll
            for (int h = 0; h < 2; h++) MMA16816(acc[h], af, &bh[h * 2]);
        }
        if (t < 63) split_sts(sm2 + nxt, areg, a_sts, 8, Y_ALO);
        CPWAIT0();
        __syncthreads();
    }
    int qr = lane >> 2, qc = lane & 3;
#pragma unroll
    for (int h = 0; h < 2; h++) {
        int m = rb + wid * 16 + qr + 8 * h;
#pragma unroll
        for (int nf = 0; nf < 2; nf++)
            *reinterpret_cast<float2*>(d_Ya + (size_t)m * 16 + nf * 8 + qc * 2) =
                make_float2(acc[nf][2 * h], acc[nf][2 * h + 1]);
    }
}

// ---------------- fused aggregation + finalize: one warp per dst node ----------------
__global__ __launch_bounds__(256) void fused_agg(const float* __restrict__ bl1,
                                                 const float* __restrict__ bla) {
    int w = (blockIdx.x * 256 + threadIdx.x) >> 5;
    if (w >= N_NODES) return;
    int lane = threadIdx.x & 31;
    int start = d_off[w], deg = d_deg[w];
    float4 a0 = make_float4(0.f, 0.f, 0.f, 0.f);
    float4 a1 = make_float4(0.f, 0.f, 0.f, 0.f);
    float acca = 0.f;
    for (int j = 0; j < deg; j++) {
        int s = d_srcs[start + j];
        const float4* ys = reinterpret_cast<const float4*>(d_Yl1 + (size_t)s * HID);
        float4 v0 = ys[lane], v1 = ys[lane + 32];
        a0.x += v0.x; a0.y += v0.y; a0.z += v0.z; a0.w += v0.w;
        a1.x += v1.x; a1.y += v1.y; a1.z += v1.z; a1.w += v1.w;
        if (lane < 8) acca += d_Ya[s * 16 + lane];
    }
    float inv = (deg > 0) ? 1.f / (float)deg : 0.f;
    const float4* yr = reinterpret_cast<const float4*>(d_Yr1 + (size_t)w * HID);
    const float4* bp = reinterpret_cast<const float4*>(bl1);
    float4 r0 = yr[lane], r1 = yr[lane + 32];
    float4 b0 = bp[lane], b1 = bp[lane + 32];
    float4 z0, z1;
    z0.x = fmaxf(a0.x * inv + b0.x + r0.x, 0.f);
    z0.y = fmaxf(a0.y * inv + b0.y + r0.y, 0.f);
    z0.z = fmaxf(a0.z * inv + b0.z + r0.z, 0.f);
    z0.w = fmaxf(a0.w * inv + b0.w + r0.w, 0.f);
    z1.x = fmaxf(a1.x * inv + b1.x + r1.x, 0.f);
    z1.y = fmaxf(a1.y * inv + b1.y + r1.y, 0.f);
    z1.z = fmaxf(a1.z * inv + b1.z + r1.z, 0.f);
    z1.w = fmaxf(a1.w * inv + b1.w + r1.w, 0.f);
    float4* zp = reinterpret_cast<float4*>(d_Z + (size_t)w * HID);
    zp[lane] = z0; zp[lane + 32] = z1;

    float sv = -1e30f;
    if (lane < 8) sv = acca * inv + bla[lane] + d_Ya[w * 16 + 8 + lane];
    float mx = sv;
    mx = fmaxf(mx, __shfl_xor_sync(0xffffffffu, mx, 4));
    mx = fmaxf(mx, __shfl_xor_sync(0xffffffffu, mx, 2));
    mx = fmaxf(mx, __shfl_xor_sync(0xffffffffu, mx, 1));
    float e = (lane < 8) ? expf(sv - mx) : 0.f;
    float ssum = e;
    ssum += __shfl_xor_sync(0xffffffffu, ssum, 4);
    ssum += __shfl_xor_sync(0xffffffffu, ssum, 2);
    ssum += __shfl_xor_sync(0xffffffffu, ssum, 1);
    if (lane < 8) d_Ss[w * NC + lane] = e / ssum;
}

// ---------------- Xp ----------------
__global__ __launch_bounds__(256) void xp_kernel() {
    int g = blockIdx.x >> 2, chunk = blockIdx.x & 3, tid = threadIdx.x;
    float acc[8];
#pragma unroll
    for (int c = 0; c < 8; c++) acc[c] = 0.f;
    int n0 = g * NPG + chunk * 250;
    for (int n = n0; n < n0 + 250; n++) {
        const float4* sp = reinterpret_cast<const float4*>(&d_Ss[n * NC]);
        float4 v0 = sp[0], v1 = sp[1];
        float z = d_Z[(size_t)n * HID + tid];
        acc[0] += v0.x * z; acc[1] += v0.y * z; acc[2] += v0.z * z; acc[3] += v0.w * z;
        acc[4] += v1.x * z; acc[5] += v1.y * z; acc[6] += v1.z * z; acc[7] += v1.w * z;
    }
#pragma unroll
    for (int c = 0; c < 8; c++)
        atomicAdd(&d_Xp[g * (NC * HID) + c * HID + tid], acc[c]);
}

// ---------------- Ap ----------------
__global__ __launch_bounds__(128) void ap_kernel(const int* __restrict__ src,
                                                 const int* __restrict__ dst) {
    __shared__ float apl[4 * NUM_GRAPHS * 64];
    int tid = threadIdx.x, wid = tid >> 5, lane = tid & 31;
    for (int i = tid; i < 4 * NUM_GRAPHS * 64; i += 128) apl[i] = 0.f;
    __syncthreads();
    float* my = apl + wid * (NUM_GRAPHS * 64);
    int gw = blockIdx.x * 4 + wid;
#pragma unroll
    for (int b = 0; b < 2; b++) {
        int e = gw * 64 + b * 32 + lane;
        int s = src[e], d = dst[e];
        for (int j = 0; j < 32; j++) {
            int sj = __shfl_sync(0xffffffffu, s, j);
            int dj = __shfl_sync(0xffffffffu, d, j);
            int gj = sj / NPG;
            float v = 0.f;
            if (lane < 8)       v = d_Ss[sj * NC + lane];
            else if (lane < 16) v = d_Ss[dj * NC + (lane - 8)];
            int a1 = lane >> 3;
            int bb = lane & 7;
            float s1 = __shfl_sync(0xffffffffu, v, a1);
            float s2 = __shfl_sync(0xffffffffu, v, a1 + 4);
            float sd = __shfl_sync(0xffffffffu, v, 8 + bb);
            float* p = my + gj * 64;
            p[lane]      += s1 * sd;
            p[lane + 32] += s2 * sd;
        }
    }
    __syncthreads();
    for (int i = tid; i < NUM_GRAPHS * 64; i += 128) {
        float a = apl[i] + apl[NUM_GRAPHS * 64 + i] +
                  apl[2 * NUM_GRAPHS * 64 + i] + apl[3 * NUM_GRAPHS * 64 + i];
        atomicAdd(&d_Ap[i], a);
    }
}

// ---------------- pooled conv + classifier ----------------
__global__ __launch_bounds__(256) void final_kernel(const float* __restrict__ Wl2,
                                                    const float* __restrict__ bl2,
                                                    const float* __restrict__ Wr2,
                                                    const float* __restrict__ Wc1,
                                                    const float* __restrict__ bc1,
                                                    const float* __restrict__ Wc2,
                                                    const float* __restrict__ bc2,
                                                    float* __restrict__ out) {
    int g = blockIdx.x, tid = threadIdx.x;
    __shared__ float maskS[64];
    __shared__ float degS[8];
    __shared__ float xps[8 * 256];
    __shared__ float a2s[8 * 256];
    __shared__ float zps[2048];
    __shared__ float red[256];

    if (tid < 64) maskS[tid] = (d_Ap[g * 64 + tid] != 0.0f) ? 1.0f : 0.0f;
    __syncthreads();
    if (tid < 8) {
        float dg = 0.f;
#pragma unroll
        for (int i = 0; i < 8; i++) dg += maskS[i * 8 + tid];
        degS[tid] = dg;
    }
#pragma unroll
    for (int c = 0; c < 8; c++)
        xps[c * 256 + tid] = d_Xp[g * 2048 + c * 256 + tid];
    __syncthreads();

#pragma unroll
    for (int j = 0; j < 8; j++) {
        float s = 0.f;
#pragma unroll
        for (int i = 0; i < 8; i++) s += maskS[i * 8 + j] * xps[i * 256 + tid];
        float dg = degS[j];
        a2s[j * 256 + tid] = (dg > 0.f) ? s / fmaxf(dg, 1.f) : 0.f;
    }
    __syncthreads();

    float acc[8];
    float bb = bl2[tid];
#pragma unroll
    for (int j = 0; j < 8; j++) acc[j] = bb;
    for (int k = 0; k < 256; k++) {
        float wl = Wl2[k * 256 + tid];
        float wr = Wr2[k * 256 + tid];
#pragma unroll
        for (int j = 0; j < 8; j++)
            acc[j] += a2s[j * 256 + k] * wl + xps[j * 256 + k] * wr;
    }
#pragma unroll
    for (int j = 0; j < 8; j++) zps[j * 256 + tid] = fmaxf(acc[j], 0.f);
    __syncthreads();

    float hacc = bc1[tid];
    for (int m = 0; m < 2048; m++) hacc += zps[m] * Wc1[m * 256 + tid];
    float hv = fmaxf(hacc, 0.f);
    red[tid] = hv * Wc2[tid];
    __syncthreads();
    for (int s = 128; s > 0; s >>= 1) {
        if (tid < s) red[tid] += red[tid + s];
        __syncthreads();
    }
    if (tid == 0) out[g] = red[0] + bc2[0];
}

// ---------------- launch ----------------
extern "C" void kernel_launch(void* const* d_in, const int* in_sizes, int n_in,
                              void* d_out, int out_size) {
    const float* x   = (const float*)d_in[0];
    const int*   ei  = (const int*)d_in[1];
    const int*   src = ei;
    const int*   dst = ei + N_EDGES;
    const float* Wl1 = (const float*)d_in[3];
    const float* bl1 = (const float*)d_in[4];
    const float* Wr1 = (const float*)d_in[5];
    const float* Wla = (const float*)d_in[6];
    const float* bla = (const float*)d_in[7];
    const float* Wra = (const float*)d_in[8];
    const float* Wl2 = (const float*)d_in[9];
    const float* bl2 = (const float*)d_in[10];
    const float* Wr2 = (const float*)d_in[11];
    const float* Wc1 = (const float*)d_in[12];
    const float* bc1 = (const float*)d_in[13];
    const float* Wc2 = (const float*)d_in[14];
    const float* bc2 = (const float*)d_in[15];
    float* out = (float*)d_out;

    cudaFuncSetAttribute(mma_gemm, cudaFuncAttributeMaxDynamicSharedMemorySize, GEMM_SMEM);

    prep_b<<<528, 256>>>(Wl1, Wr1, Wla, Wra);
    zero_kernel<<<128, 256>>>();
    hist_kernel<<<256, 256>>>(dst);
    scan_kernel<<<1, 1024>>>();
    scatter_kernel<<<256, 256>>>(src, dst);
    mma_gemm<<<dim3(250, 2), 256, GEMM_SMEM>>>(x);
    ya_gemm<<<250, 256>>>(x);
    fused_agg<<<4000, 256>>>(bl1, bla);
    xp_kernel<<<128, 256>>>();
    ap_kernel<<<1000, 128>>>(src, dst);
    final_kernel<<<32, 256>>>(Wl2, bl2, Wr2, Wc1, bc1, Wc2, bc2, out);
}

// round 7
// speedup vs baseline: 1.6664x; 1.0587x over previous
#include <cuda_runtime.h>
#include <cuda_bf16.h>
#include <cstdint>

// ---------------- problem constants ----------------
#define N_NODES   32000
#define NUM_GRAPHS 32
#define NPG       1000
#define N_EDGES   256000
#define IN_DIM    1024
#define HID       256
#define NC        8

// ---------------- scratch (device globals) ----------------
__device__ float d_Yl1 [N_NODES * HID];
__device__ float d_Yr1 [N_NODES * HID];
__device__ float d_Ya  [N_NODES * 16];
__device__ float d_Z   [N_NODES * HID];
__device__ float d_Ss  [N_NODES * NC];
__device__ float d_Xp  [NUM_GRAPHS * NC * HID];
__device__ float d_Ap  [NUM_GRAPHS * NC * NC];
__device__ __nv_bfloat16 d_Bhi[528 * 1024];
__device__ __nv_bfloat16 d_Blo[528 * 1024];
// CSR for dst-sorted edges
__device__ int d_deg [N_NODES];
__device__ int d_off [N_NODES];
__device__ int d_cur [N_NODES];
__device__ int d_srcs[N_EDGES];

// =============== helpers (sm_80-era PTX: valid under compute_100) ===============
static __device__ __forceinline__ uint32_t s2u(const void* p) {
    uint32_t a;
    asm("{ .reg .u64 t; cvta.to.shared.u64 t, %1; cvt.u32.u64 %0, t; }" : "=r"(a) : "l"(p));
    return a;
}
#define LDMX4(r0, r1, r2, r3, addr) \
    asm volatile("ldmatrix.sync.aligned.m8n8.x4.shared.b16 {%0,%1,%2,%3}, [%4];" \
        : "=r"(r0), "=r"(r1), "=r"(r2), "=r"(r3) : "r"(addr))
#define MMA16816(c, a, b) \
    asm volatile("mma.sync.aligned.m16n8k16.row.col.f32.bf16.bf16.f32 " \
        "{%0,%1,%2,%3}, {%4,%5,%6,%7}, {%8,%9}, {%0,%1,%2,%3};" \
        : "+f"((c)[0]), "+f"((c)[1]), "+f"((c)[2]), "+f"((c)[3]) \
        : "r"((a)[0]), "r"((a)[1]), "r"((a)[2]), "r"((a)[3]), "r"((b)[0]), "r"((b)[1]))
#define CP16(dst, src) \
    asm volatile("cp.async.cg.shared.global [%0], [%1], 16;" :: "r"(dst), "l"(src))
#define CPCOMMIT() asm volatile("cp.async.commit_group;" ::: "memory")
#define CPWAIT0()  asm volatile("cp.async.wait_group 0;" ::: "memory")

// ---------------- zero small accumulators ----------------
__global__ __launch_bounds__(256) void zero_kernel() {
    int t = blockIdx.x * blockDim.x + threadIdx.x;
    int stride = gridDim.x * blockDim.x;
    for (int i = t; i < N_NODES; i += stride) d_deg[i] = 0;
    for (int i = t; i < NUM_GRAPHS * NC * HID; i += stride) d_Xp[i] = 0.f;
    for (int i = t; i < NUM_GRAPHS * NC * NC;  i += stride) d_Ap[i] = 0.f;
}

// ---------------- weight prep: coalesced transpose + bf16 hi/lo split ----------------
// d_Bhi/d_Blo row n (output col), 1024 contiguous k.
// grid 17: blocks 0-7 Wl1 (n 0-255), 8-15 Wr1 (n 256-511), 16 Wla+Wra (n 512-527).
__global__ __launch_bounds__(256) void prep_b(const float* __restrict__ Wl1,
                                              const float* __restrict__ Wr1,
                                              const float* __restrict__ Wla,
                                              const float* __restrict__ Wra) {
    int b = blockIdx.x, tid = threadIdx.x;
    if (b < 16) {
        __shared__ float tile[64][33];
        const float* W = (b < 8) ? Wl1 : Wr1;
        int ncol0 = (b & 7) * 32;
        int nout0 = (b < 8) ? ncol0 : 256 + ncol0;
        int tk8 = tid >> 5, tn = tid & 31;
        int n = tid >> 3, kq = (tid & 7) * 8;
        for (int k0 = 0; k0 < IN_DIM; k0 += 64) {
#pragma unroll
            for (int j = 0; j < 8; j++)
                tile[tk8 * 8 + j][tn] = W[(size_t)(k0 + tk8 * 8 + j) * 256 + ncol0 + tn];
            __syncthreads();
            uint32_t hi[4], lo[4];
#pragma unroll
            for (int q = 0; q < 4; q++) {
                float f0 = tile[kq + 2 * q][n], f1 = tile[kq + 2 * q + 1][n];
                __nv_bfloat162 hp, lp;
                hp.x = __float2bfloat16(f0); hp.y = __float2bfloat16(f1);
                lp.x = __float2bfloat16(f0 - __bfloat162float(hp.x));
                lp.y = __float2bfloat16(f1 - __bfloat162float(hp.y));
                hi[q] = *reinterpret_cast<uint32_t*>(&hp);
                lo[q] = *reinterpret_cast<uint32_t*>(&lp);
            }
            *reinterpret_cast<uint4*>((char*)d_Bhi + ((size_t)(nout0 + n) * IN_DIM + k0 + kq) * 2) =
                make_uint4(hi[0], hi[1], hi[2], hi[3]);
            *reinterpret_cast<uint4*>((char*)d_Blo + ((size_t)(nout0 + n) * IN_DIM + k0 + kq) * 2) =
                make_uint4(lo[0], lo[1], lo[2], lo[3]);
            __syncthreads();
        }
    } else {
        // 16 small columns (Wla n=512-519, Wra n=520-527)
        for (int idx = tid; idx < 16 * IN_DIM; idx += 256) {
            int n = idx & 15, k = idx >> 4;
            float w = (n < 8) ? Wla[k * 8 + n] : Wra[k * 8 + (n - 8)];
            __nv_bfloat16 h = __float2bfloat16(w);
            d_Bhi[(size_t)(512 + n) * IN_DIM + k] = h;
            d_Blo[(size_t)(512 + n) * IN_DIM + k] = __float2bfloat16(w - __bfloat162float(h));
        }
    }
}

// ---------------- CSR build ----------------
__global__ __launch_bounds__(256) void hist_kernel(const int* __restrict__ dst) {
    int t = blockIdx.x * blockDim.x + threadIdx.x;
    int stride = gridDim.x * blockDim.x;
    for (int e = t; e < N_EDGES; e += stride) atomicAdd(&d_deg[dst[e]], 1);
}

// parallel scan: 32 blocks, one per graph. Block g: base = sum(deg[0, g*1000)),
// then shared-mem scan of its own 1000 degrees.
__global__ __launch_bounds__(256) void scan_kernel() {
    __shared__ int sums[256];
    __shared__ int base_sh;
    int g = blockIdx.x, tid = threadIdx.x;
    int s = 0;
    for (int i = tid; i < g * NPG; i += 256) s += d_deg[i];
    sums[tid] = s;
    __syncthreads();
    for (int st = 128; st > 0; st >>= 1) {
        if (tid < st) sums[tid] += sums[tid + st];
        __syncthreads();
    }
    if (tid == 0) base_sh = sums[0];
    __syncthreads();
    int base = base_sh;
    __syncthreads();
    int v[4], loc = 0;
#pragma unroll
    for (int j = 0; j < 4; j++) {
        int i = tid * 4 + j;
        v[j] = (i < NPG) ? d_deg[g * NPG + i] : 0;
        loc += v[j];
    }
    sums[tid] = loc;
    __syncthreads();
    for (int off = 1; off < 256; off <<= 1) {
        int t2 = (tid >= off) ? sums[tid - off] : 0;
        __syncthreads();
        sums[tid] += t2;
        __syncthreads();
    }
    int excl = base + ((tid == 0) ? 0 : sums[tid - 1]);
#pragma unroll
    for (int j = 0; j < 4; j++) {
        int i = tid * 4 + j;
        if (i < NPG) {
            d_off[g * NPG + i] = excl;
            d_cur[g * NPG + i] = excl;
            excl += v[j];
        }
    }
}

__global__ __launch_bounds__(256) void scatter_kernel(const int* __restrict__ src,
                                                      const int* __restrict__ dst) {
    int t = blockIdx.x * blockDim.x + threadIdx.x;
    int stride = gridDim.x * blockDim.x;
    for (int e = t; e < N_EDGES; e += stride) {
        int pos = atomicAdd(&d_cur[dst[e]], 1);
        d_srcs[pos] = src[e];
    }
}

// ---------------- main tensor-core GEMM ----------------
// C[32000,256] = X[32000,1024] @ W^T, split-bf16 (3 products). grid (2, 250):
// x = which weight (0: Wl1, 1: Wr1), y = row block — adjacent CTAs share the A tile in L2.
#define PADA 40
#define A_SZ (128 * PADA * 2)              // 10240 B per split
#define B_SZ (256 * PADA * 2)              // 20480 B per split
#define OFF_ALO A_SZ
#define OFF_BHI (2 * A_SZ)
#define OFF_BLO (2 * A_SZ + B_SZ)
#define STG (2 * A_SZ + 2 * B_SZ)          // 61440
#define GEMM_SMEM (2 * STG)                // 122880

// store nfl floats as hi/lo bf16; lo region begins at stage+lo_off
static __device__ __forceinline__ void split_sts(char* stage, const float* areg,
                                                 uint32_t off, int nfl, uint32_t lo_off) {
    uint32_t hi[8], lo[8];
#pragma unroll
    for (int j = 0; j < 8; j++) {
        if (j * 2 >= nfl) break;
        __nv_bfloat162 hp, lp;
        float f0 = areg[2 * j], f1 = areg[2 * j + 1];
        hp.x = __float2bfloat16(f0);
        hp.y = __float2bfloat16(f1);
        lp.x = __float2bfloat16(f0 - __bfloat162float(hp.x));
        lp.y = __float2bfloat16(f1 - __bfloat162float(hp.y));
        hi[j] = *reinterpret_cast<uint32_t*>(&hp);
        lo[j] = *reinterpret_cast<uint32_t*>(&lp);
    }
    *reinterpret_cast<uint4*>(stage + off)           = make_uint4(hi[0], hi[1], hi[2], hi[3]);
    *reinterpret_cast<uint4*>(stage + lo_off + off)  = make_uint4(lo[0], lo[1], lo[2], lo[3]);
    if (nfl == 16) {
        *reinterpret_cast<uint4*>(stage + off + 16)          = make_uint4(hi[4], hi[5], hi[6], hi[7]);
        *reinterpret_cast<uint4*>(stage + lo_off + off + 16) = make_uint4(lo[4], lo[5], lo[6], lo[7]);
    }
}

__global__ __launch_bounds__(256, 1) void mma_gemm(const float* __restrict__ X) {
    extern __shared__ char sm[];
    uint32_t sb = s2u(sm);
    int tid = threadIdx.x, lane = tid & 31, wid = tid >> 5;
    int rb = blockIdx.y * 128, yt = blockIdx.x;

    // loader roles
    int arow = tid >> 1, ahalf = (tid & 1) * 16;
    const float* aptr = X + (size_t)(rb + arow) * IN_DIM + ahalf;
    uint32_t a_sts = (uint32_t)(arow * PADA + ahalf) * 2;
    const char* bh_g = (const char*)(d_Bhi + ((size_t)yt * 256 + tid) * IN_DIM);
    const char* bl_g = (const char*)(d_Blo + ((size_t)yt * 256 + tid) * IN_DIM);
    uint32_t b_sts = (uint32_t)(tid * PADA) * 2;

    // compute addressing
    int wm = wid >> 2, wn = wid & 3;
    int tl = lane >> 3, tr = lane & 7;
    uint32_t a_off[4], b_off[4];
#pragma unroll
    for (int mf = 0; mf < 4; mf++) {
        int m_loc = wm * 64 + mf * 16 + (tl & 1) * 8 + tr;
        a_off[mf] = (uint32_t)(m_loc * PADA + (tl >> 1) * 8) * 2;
    }
#pragma unroll
    for (int ng = 0; ng < 4; ng++) {
        int n_loc = wn * 64 + ng * 16 + (tl >> 1) * 8 + tr;
        b_off[ng] = (uint32_t)(n_loc * PADA + (tl & 1) * 8) * 2;
    }

    float acc[4][8][4];
#pragma unroll
    for (int i = 0; i < 4; i++)
#pragma unroll
        for (int j = 0; j < 8; j++)
#pragma unroll
            for (int k = 0; k < 4; k++) acc[i][j][k] = 0.f;

    float areg[16];
    // ---- prologue: tile 0 ----
    {
        const float4* p = (const float4*)aptr;
#pragma unroll
        for (int i = 0; i < 4; i++) {
            float4 v = p[i];
            areg[4 * i] = v.x; areg[4 * i + 1] = v.y; areg[4 * i + 2] = v.z; areg[4 * i + 3] = v.w;
        }
#pragma unroll
        for (int i = 0; i < 4; i++) {
            CP16(sb + OFF_BHI + b_sts + i * 16, bh_g + i * 16);
            CP16(sb + OFF_BLO + b_sts + i * 16, bl_g + i * 16);
        }
        CPCOMMIT();
        split_sts(sm, areg, a_sts, 16, OFF_ALO);
        CPWAIT0();
        __syncthreads();
    }

    for (int t = 0; t < 32; t++) {
        uint32_t cur = (uint32_t)(t & 1) * STG;
        uint32_t nxt = (uint32_t)((t + 1) & 1) * STG;
        if (t < 31) {
            const float4* p = (const float4*)(aptr + (t + 1) * 32);
#pragma unroll
            for (int i = 0; i < 4; i++) {
                float4 v = p[i];
                areg[4 * i] = v.x; areg[4 * i + 1] = v.y; areg[4 * i + 2] = v.z; areg[4 * i + 3] = v.w;
            }
#pragma unroll
            for (int i = 0; i < 4; i++) {
                CP16(sb + nxt + OFF_BHI + b_sts + i * 16, bh_g + (size_t)(t + 1) * 64 + i * 16);
                CP16(sb + nxt + OFF_BLO + b_sts + i * 16, bl_g + (size_t)(t + 1) * 64 + i * 16);
            }
            CPCOMMIT();
        }
        uint32_t stb = sb + cur;
#pragma unroll
        for (int kk = 0; kk < 2; kk++) {
            uint32_t kb = kk * 32;
            uint32_t bh[4][4], blr[4][4], af[4][4];
#pragma unroll
            for (int ng = 0; ng < 4; ng++)
                LDMX4(bh[ng][0], bh[ng][1], bh[ng][2], bh[ng][3], stb + OFF_BHI + b_off[ng] + kb);
#pragma unroll
            for (int ng = 0; ng < 4; ng++)
                LDMX4(blr[ng][0], blr[ng][1], blr[ng][2], blr[ng][3], stb + OFF_BLO + b_off[ng] + kb);
#pragma unroll
            for (int mf = 0; mf < 4; mf++)
                LDMX4(af[mf][0], af[mf][1], af[mf][2], af[mf][3], stb + a_off[mf] + kb);
#pragma unroll
            for (int mf = 0; mf < 4; mf++)
#pragma unroll
                for (int ng = 0; ng < 4; ng++)
#pragma unroll
                    for (int h = 0; h < 2; h++)
                        MMA16816(acc[mf][ng * 2 + h], af[mf], &bh[ng][h * 2]);
#pragma unroll
            for (int mf = 0; mf < 4; mf++)
#pragma unroll
                for (int ng = 0; ng < 4; ng++)
#pragma unroll
                    for (int h = 0; h < 2; h++)
                        MMA16816(acc[mf][ng * 2 + h], af[mf], &blr[ng][h * 2]);
#pragma unroll
            for (int mf = 0; mf < 4; mf++)
                LDMX4(af[mf][0], af[mf][1], af[mf][2], af[mf][3], stb + OFF_ALO + a_off[mf] + kb);
#pragma unroll
            for (int mf = 0; mf < 4; mf++)
#pragma unroll
                for (int ng = 0; ng < 4; ng++)
#pragma unroll
                    for (int h = 0; h < 2; h++)
                        MMA16816(acc[mf][ng * 2 + h], af[mf], &bh[ng][h * 2]);
        }
        if (t < 31) split_sts(sm + nxt, areg, a_sts, 16, OFF_ALO);
        CPWAIT0();
        __syncthreads();
    }

    // ---- epilogue: direct global stores ----
    float* outp = yt ? d_Yr1 : d_Yl1;
    int qr = lane >> 2, qc = lane & 3;
#pragma unroll
    for (int mf = 0; mf < 4; mf++)
#pragma unroll
        for (int h = 0; h < 2; h++) {
            int m = rb + wm * 64 + mf * 16 + qr + 8 * h;
            float* orow = outp + (size_t)m * HID + wn * 64 + qc * 2;
#pragma unroll
            for (int nf = 0; nf < 8; nf++)
                *reinterpret_cast<float2*>(orow + nf * 8) =
                    make_float2(acc[mf][nf][2 * h], acc[mf][nf][2 * h + 1]);
        }
}

// ---------------- Ya GEMM: [32000,16] = X @ [Wla|Wra], mma split-bf16 ----------------
#define PAD2 24
#define A2_SZ (128 * PAD2 * 2)             // 6144
#define B2_SZ (16 * PAD2 * 2)              // 768
#define Y_ALO A2_SZ
#define Y_BHI (2 * A2_SZ)
#define Y_BLO (2 * A2_SZ + B2_SZ)
#define STG2 (2 * A2_SZ + 2 * B2_SZ)       // 13824

__global__ __launch_bounds__(256) void ya_gemm(const float* __restrict__ X) {
    __shared__ char sm2[2 * STG2];
    uint32_t sb = s2u(sm2);
    int tid = threadIdx.x, lane = tid & 31, wid = tid >> 5;
    int rb = blockIdx.x * 128;

    int arow = tid >> 1, ahalf = (tid & 1) * 8;
    const float* aptr = X + (size_t)(rb + arow) * IN_DIM + ahalf;
    uint32_t a_sts = (uint32_t)(arow * PAD2 + ahalf) * 2;

    int isb = (tid < 64);
    int bs = tid >> 5;           // 0 = hi, 1 = lo (valid when tid<64)
    int bi = tid & 31, brow = bi >> 1, bc = bi & 1;
    const char* bg = (const char*)((bs ? d_Blo : d_Bhi) + (size_t)(512 + brow) * IN_DIM);
    uint32_t b_sts = (bs ? Y_BLO : Y_BHI) + (uint32_t)(brow * PAD2 + bc * 8) * 2;

    int tl = lane >> 3, tr = lane & 7;
    uint32_t a_off = (uint32_t)((wid * 16 + (tl & 1) * 8 + tr) * PAD2 + (tl >> 1) * 8) * 2;
    uint32_t b_off = (uint32_t)(((tl >> 1) * 8 + tr) * PAD2 + (tl & 1) * 8) * 2;

    float acc[2][4];
#pragma unroll
    for (int i = 0; i < 2; i++)
#pragma unroll
        for (int k = 0; k < 4; k++) acc[i][k] = 0.f;

    float areg[8];
    {
        const float4* p = (const float4*)aptr;
#pragma unroll
        for (int i = 0; i < 2; i++) {
            float4 v = p[i];
            areg[4 * i] = v.x; areg[4 * i + 1] = v.y; areg[4 * i + 2] = v.z; areg[4 * i + 3] = v.w;
        }
        if (isb) CP16(sb + b_sts, bg + bc * 16);
        CPCOMMIT();
        split_sts(sm2, areg, a_sts, 8, Y_ALO);
        CPWAIT0();
        __syncthreads();
    }
    for (int t = 0; t < 64; t++) {
        uint32_t cur = (uint32_t)(t & 1) * STG2;
        uint32_t nxt = (uint32_t)((t + 1) & 1) * STG2;
        if (t < 63) {
            const float4* p = (const float4*)(aptr + (t + 1) * 16);
#pragma unroll
            for (int i = 0; i < 2; i++) {
                float4 v = p[i];
                areg[4 * i] = v.x; areg[4 * i + 1] = v.y; areg[4 * i + 2] = v.z; areg[4 * i + 3] = v.w;
            }
            if (isb) CP16(sb + nxt + b_sts, bg + (size_t)(t + 1) * 32 + bc * 16);
            CPCOMMIT();
        }
        uint32_t stb = sb + cur;
        {
            uint32_t bh[4], bl4[4], af[4];
            LDMX4(bh[0], bh[1], bh[2], bh[3], stb + Y_BHI + b_off);
            LDMX4(bl4[0], bl4[1], bl4[2], bl4[3], stb + Y_BLO + b_off);
            LDMX4(af[0], af[1], af[2], af[3], stb + a_off);
#pragma unroll
            for (int h = 0; h < 2; h++) {
                MMA16816(acc[h], af, &bh[h * 2]);
                MMA16816(acc[h], af, &bl4[h * 2]);
            }
            LDMX4(af[0], af[1], af[2], af[3], stb + Y_ALO + a_off);
#pragma unroll
            for (int h = 0; h < 2; h++) MMA16816(acc[h], af, &bh[h * 2]);
        }
        if (t < 63) split_sts(sm2 + nxt, areg, a_sts, 8, Y_ALO);
        CPWAIT0();
        __syncthreads();
    }
    int qr = lane >> 2, qc = lane & 3;
#pragma unroll
    for (int h = 0; h < 2; h++) {
        int m = rb + wid * 16 + qr + 8 * h;
#pragma unroll
        for (int nf = 0; nf < 2; nf++)
            *reinterpret_cast<float2*>(d_Ya + (size_t)m * 16 + nf * 8 + qc * 2) =
                make_float2(acc[nf][2 * h], acc[nf][2 * h + 1]);
    }
}

// ---------------- fused aggregation + finalize: one warp per dst node ----------------
__global__ __launch_bounds__(256) void fused_agg(const float* __restrict__ bl1,
                                                 const float* __restrict__ bla) {
    int w = (blockIdx.x * 256 + threadIdx.x) >> 5;
    if (w >= N_NODES) return;
    int lane = threadIdx.x & 31;
    int start = d_off[w], deg = d_deg[w];
    float4 a0 = make_float4(0.f, 0.f, 0.f, 0.f);
    float4 a1 = make_float4(0.f, 0.f, 0.f, 0.f);
    float acca = 0.f;
    for (int j = 0; j < deg; j++) {
        int s = d_srcs[start + j];
        const float4* ys = reinterpret_cast<const float4*>(d_Yl1 + (size_t)s * HID);
        float4 v0 = ys[lane], v1 = ys[lane + 32];
        a0.x += v0.x; a0.y += v0.y; a0.z += v0.z; a0.w += v0.w;
        a1.x += v1.x; a1.y += v1.y; a1.z += v1.z; a1.w += v1.w;
        if (lane < 8) acca += d_Ya[s * 16 + lane];
    }
    float inv = (deg > 0) ? 1.f / (float)deg : 0.f;
    const float4* yr = reinterpret_cast<const float4*>(d_Yr1 + (size_t)w * HID);
    const float4* bp = reinterpret_cast<const float4*>(bl1);
    float4 r0 = yr[lane], r1 = yr[lane + 32];
    float4 b0 = bp[lane], b1 = bp[lane + 32];
    float4 z0, z1;
    z0.x = fmaxf(a0.x * inv + b0.x + r0.x, 0.f);
    z0.y = fmaxf(a0.y * inv + b0.y + r0.y, 0.f);
    z0.z = fmaxf(a0.z * inv + b0.z + r0.z, 0.f);
    z0.w = fmaxf(a0.w * inv + b0.w + r0.w, 0.f);
    z1.x = fmaxf(a1.x * inv + b1.x + r1.x, 0.f);
    z1.y = fmaxf(a1.y * inv + b1.y + r1.y, 0.f);
    z1.z = fmaxf(a1.z * inv + b1.z + r1.z, 0.f);
    z1.w = fmaxf(a1.w * inv + b1.w + r1.w, 0.f);
    float4* zp = reinterpret_cast<float4*>(d_Z + (size_t)w * HID);
    zp[lane] = z0; zp[lane + 32] = z1;

    float sv = -1e30f;
    if (lane < 8) sv = acca * inv + bla[lane] + d_Ya[w * 16 + 8 + lane];
    float mx = sv;
    mx = fmaxf(mx, __shfl_xor_sync(0xffffffffu, mx, 4));
    mx = fmaxf(mx, __shfl_xor_sync(0xffffffffu, mx, 2));
    mx = fmaxf(mx, __shfl_xor_sync(0xffffffffu, mx, 1));
    float e = (lane < 8) ? expf(sv - mx) : 0.f;
    float ssum = e;
    ssum += __shfl_xor_sync(0xffffffffu, ssum, 4);
    ssum += __shfl_xor_sync(0xffffffffu, ssum, 2);
    ssum += __shfl_xor_sync(0xffffffffu, ssum, 1);
    if (lane < 8) d_Ss[w * NC + lane] = e / ssum;
}

// ---------------- Xp ----------------
__global__ __launch_bounds__(256) void xp_kernel() {
    int g = blockIdx.x >> 2, chunk = blockIdx.x & 3, tid = threadIdx.x;
    float acc[8];
#pragma unroll
    for (int c = 0; c < 8; c++) acc[c] = 0.f;
    int n0 = g * NPG + chunk * 250;
    for (int n = n0; n < n0 + 250; n++) {
        const float4* sp = reinterpret_cast<const float4*>(&d_Ss[n * NC]);
        float4 v0 = sp[0], v1 = sp[1];
        float z = d_Z[(size_t)n * HID + tid];
        acc[0] += v0.x * z; acc[1] += v0.y * z; acc[2] += v0.z * z; acc[3] += v0.w * z;
        acc[4] += v1.x * z; acc[5] += v1.y * z; acc[6] += v1.z * z; acc[7] += v1.w * z;
    }
#pragma unroll
    for (int c = 0; c < 8; c++)
        atomicAdd(&d_Xp[g * (NC * HID) + c * HID + tid], acc[c]);
}

// ---------------- Ap ----------------
__global__ __launch_bounds__(128) void ap_kernel(const int* __restrict__ src,
                                                 const int* __restrict__ dst) {
    __shared__ float apl[4 * NUM_GRAPHS * 64];
    int tid = threadIdx.x, wid = tid >> 5, lane = tid & 31;
    for (int i = tid; i < 4 * NUM_GRAPHS * 64; i += 128) apl[i] = 0.f;
    __syncthreads();
    float* my = apl + wid * (NUM_GRAPHS * 64);
    int gw = blockIdx.x * 4 + wid;
#pragma unroll
    for (int b = 0; b < 2; b++) {
        int e = gw * 64 + b * 32 + lane;
        int s = src[e], d = dst[e];
        for (int j = 0; j < 32; j++) {
            int sj = __shfl_sync(0xffffffffu, s, j);
            int dj = __shfl_sync(0xffffffffu, d, j);
            int gj = sj / NPG;
            float v = 0.f;
            if (lane < 8)       v = d_Ss[sj * NC + lane];
            else if (lane < 16) v = d_Ss[dj * NC + (lane - 8)];
            int a1 = lane >> 3;
            int bb = lane & 7;
            float s1 = __shfl_sync(0xffffffffu, v, a1);
            float s2 = __shfl_sync(0xffffffffu, v, a1 + 4);
            float sd = __shfl_sync(0xffffffffu, v, 8 + bb);
            float* p = my + gj * 64;
            p[lane]      += s1 * sd;
            p[lane + 32] += s2 * sd;
        }
    }
    __syncthreads();
    for (int i = tid; i < NUM_GRAPHS * 64; i += 128) {
        float a = apl[i] + apl[NUM_GRAPHS * 64 + i] +
                  apl[2 * NUM_GRAPHS * 64 + i] + apl[3 * NUM_GRAPHS * 64 + i];
        atomicAdd(&d_Ap[i], a);
    }
}

// ---------------- pooled conv + classifier ----------------
__global__ __launch_bounds__(256) void final_kernel(const float* __restrict__ Wl2,
                                                    const float* __restrict__ bl2,
                                                    const float* __restrict__ Wr2,
                                                    const float* __restrict__ Wc1,
                                                    const float* __restrict__ bc1,
                                                    const float* __restrict__ Wc2,
                                                    const float* __restrict__ bc2,
                                                    float* __restrict__ out) {
    int g = blockIdx.x, tid = threadIdx.x;
    __shared__ float maskS[64];
    __shared__ float degS[8];
    __shared__ float xps[8 * 256];
    __shared__ float a2s[8 * 256];
    __shared__ float zps[2048];
    __shared__ float red[256];

    if (tid < 64) maskS[tid] = (d_Ap[g * 64 + tid] != 0.0f) ? 1.0f : 0.0f;
    __syncthreads();
    if (tid < 8) {
        float dg = 0.f;
#pragma unroll
        for (int i = 0; i < 8; i++) dg += maskS[i * 8 + tid];
        degS[tid] = dg;
    }
#pragma unroll
    for (int c = 0; c < 8; c++)
        xps[c * 256 + tid] = d_Xp[g * 2048 + c * 256 + tid];
    __syncthreads();

#pragma unroll
    for (int j = 0; j < 8; j++) {
        float s = 0.f;
#pragma unroll
        for (int i = 0; i < 8; i++) s += maskS[i * 8 + j] * xps[i * 256 + tid];
        float dg = degS[j];
        a2s[j * 256 + tid] = (dg > 0.f) ? s / fmaxf(dg, 1.f) : 0.f;
    }
    __syncthreads();

    float acc[8];
    float bb = bl2[tid];
#pragma unroll
    for (int j = 0; j < 8; j++) acc[j] = bb;
    for (int k = 0; k < 256; k++) {
        float wl = Wl2[k * 256 + tid];
        float wr = Wr2[k * 256 + tid];
#pragma unroll
        for (int j = 0; j < 8; j++)
            acc[j] += a2s[j * 256 + k] * wl + xps[j * 256 + k] * wr;
    }
#pragma unroll
    for (int j = 0; j < 8; j++) zps[j * 256 + tid] = fmaxf(acc[j], 0.f);
    __syncthreads();

    float hacc = bc1[tid];
    for (int m = 0; m < 2048; m++) hacc += zps[m] * Wc1[m * 256 + tid];
    float hv = fmaxf(hacc, 0.f);
    red[tid] = hv * Wc2[tid];
    __syncthreads();
    for (int s = 128; s > 0; s >>= 1) {
        if (tid < s) red[tid] += red[tid + s];
        __syncthreads();
    }
    if (tid == 0) out[g] = red[0] + bc2[0];
}

// ---------------- launch ----------------
extern "C" void kernel_launch(void* const* d_in, const int* in_sizes, int n_in,
                              void* d_out, int out_size) {
    const float* x   = (const float*)d_in[0];
    const int*   ei  = (const int*)d_in[1];
    const int*   src = ei;
    const int*   dst = ei + N_EDGES;
    const float* Wl1 = (const float*)d_in[3];
    const float* bl1 = (const float*)d_in[4];
    const float* Wr1 = (const float*)d_in[5];
    const float* Wla = (const float*)d_in[6];
    const float* bla = (const float*)d_in[7];
    const float* Wra = (const float*)d_in[8];
    const float* Wl2 = (const float*)d_in[9];
    const float* bl2 = (const float*)d_in[10];
    const float* Wr2 = (const float*)d_in[11];
    const float* Wc1 = (const float*)d_in[12];
    const float* bc1 = (const float*)d_in[13];
    const float* Wc2 = (const float*)d_in[14];
    const float* bc2 = (const float*)d_in[15];
    float* out = (float*)d_out;

    cudaFuncSetAttribute(mma_gemm, cudaFuncAttributeMaxDynamicSharedMemorySize, GEMM_SMEM);

    // order chosen so the GEMM sits where ncu's -s window lands (profiling round 8)
    prep_b<<<17, 256>>>(Wl1, Wr1, Wla, Wra);
    zero_kernel<<<128, 256>>>();
    hist_kernel<<<256, 256>>>(dst);
    mma_gemm<<<dim3(2, 250), 256, GEMM_SMEM>>>(x);
    ya_gemm<<<250, 256>>>(x);
    scan_kernel<<<32, 256>>>();
    scatter_kernel<<<256, 256>>>(src, dst);
    fused_agg<<<4000, 256>>>(bl1, bla);
    xp_kernel<<<128, 256>>>();
    ap_kernel<<<1000, 128>>>(src, dst);
    final_kernel<<<32, 256>>>(Wl2, bl2, Wr2, Wc1, bc1, Wc2, bc2, out);
}